// round 4
// baseline (speedup 1.0000x reference)
#include <cuda_runtime.h>
#include <math.h>

// Inputs (metadata order):
// 0 tag_ids[386] i32, 1 word_ids[386] i32, 2 tag_emb[50,128], 3 word_emb[10000,384],
// 4 Wf_ih[2048,512], 5 Wf_hh[2048,512], 6 bf[2048], 7 Wb_ih[2048,512], 8 Wb_hh[2048,512], 9 bb[2048],
// 10 W1[1024,1024], 11 b1[1024], 12 W2[1024,128], 13 b2[128],
// 14 V1[1024,1024], 15 c1[1024], 16 V2[1024,1], 17 c2[1]
// Output: [73920, 129] f32

#define TT 386
#define HH 512
#define G4 2048
#define NP1 385
#define OUTC 129
#define LSTM_BD 32   // blocks per direction

// ------------- device scratch (no mallocs allowed) -------------
__device__ float d_x[TT * 512];
__device__ float d_gx[2][TT * G4];
__device__ float d_states[2][TT * HH];   // [0]=fwd[t], [1]=bwd[t] (original time index)
__device__ unsigned int d_flag[2][LSTM_BD];
__device__ float d_E[NP1 * 1024];
__device__ float d_F[NP1 * 1024];

static __device__ __forceinline__ float4 f4add(float4 a, float4 b) {
    return make_float4(a.x + b.x, a.y + b.y, a.z + b.z, a.w + b.w);
}
static __device__ __forceinline__ float4 f4sub(float4 a, float4 b) {
    return make_float4(a.x - b.x, a.y - b.y, a.z - b.z, a.w - b.w);
}
static __device__ __forceinline__ float4 f4relu(float4 a) {
    return make_float4(fmaxf(a.x, 0.f), fmaxf(a.y, 0.f), fmaxf(a.z, 0.f), fmaxf(a.w, 0.f));
}

static __device__ __forceinline__ unsigned int ld_acquire(const unsigned int* p) {
    unsigned int v;
    asm volatile("ld.acquire.gpu.global.u32 %0, [%1];" : "=r"(v) : "l"(p) : "memory");
    return v;
}
static __device__ __forceinline__ void st_release(unsigned int* p, unsigned int v) {
    asm volatile("st.release.gpu.global.u32 [%0], %1;" :: "l"(p), "r"(v) : "memory");
}

// ---------------- embed: x[t] = [tag_emb[tag], word_emb[word]]; also reset flags ----------------
__global__ void embed_kernel(const int* __restrict__ tag_ids, const int* __restrict__ word_ids,
                             const float* __restrict__ tag_emb, const float* __restrict__ word_emb) {
    int t = blockIdx.x;
    int tid = threadIdx.x;  // 128 threads: 128 float4 = 512 floats
    if (t == 0 && tid < 2 * LSTM_BD) ((unsigned int*)d_flag)[tid] = 0u;
    int tg = tag_ids[t], wd = word_ids[t];
    float4 v;
    if (tid < 32) v = ((const float4*)(tag_emb + (size_t)tg * 128))[tid];
    else          v = ((const float4*)(word_emb + (size_t)wd * 384))[tid - 32];
    ((float4*)(d_x + (size_t)t * 512))[tid] = v;
}

// ---------------- gx = x @ W_ih^T + b,  both directions ----------------
// grid: (32 jtiles of 64, 13 ttiles of 32, 2 dirs), 256 threads
__global__ __launch_bounds__(256) void gx_kernel(const float* __restrict__ Wf, const float* __restrict__ bfv,
                                                 const float* __restrict__ Wb, const float* __restrict__ bbv) {
    int dir = blockIdx.z;
    const float* W = dir ? Wb : Wf;
    const float* bias = dir ? bbv : bfv;
    int j0 = blockIdx.x * 64;
    int t0 = blockIdx.y * 32;
    __shared__ float xs[32][65];
    __shared__ float ws[64][65];
    int tid = threadIdx.x;
    int tt = tid >> 5, tj = tid & 31;
    float acc[4][2] = {};
    for (int kc = 0; kc < 8; kc++) {
#pragma unroll
        for (int i = 0; i < 2; i++) {
            int fi = tid + i * 256;           // 512 float4 of x tile
            int row = fi >> 4, q = fi & 15;
            float4 v = make_float4(0.f, 0.f, 0.f, 0.f);
            if (t0 + row < TT) v = *(const float4*)&d_x[(size_t)(t0 + row) * 512 + kc * 64 + q * 4];
            xs[row][q * 4 + 0] = v.x; xs[row][q * 4 + 1] = v.y;
            xs[row][q * 4 + 2] = v.z; xs[row][q * 4 + 3] = v.w;
        }
#pragma unroll
        for (int i = 0; i < 4; i++) {
            int fi = tid + i * 256;           // 1024 float4 of W tile [64j][64k]
            int j = fi >> 4, q = fi & 15;
            float4 v = *(const float4*)&W[(size_t)(j0 + j) * 512 + kc * 64 + q * 4];
            ws[j][q * 4 + 0] = v.x; ws[j][q * 4 + 1] = v.y;
            ws[j][q * 4 + 2] = v.z; ws[j][q * 4 + 3] = v.w;
        }
        __syncthreads();
#pragma unroll 8
        for (int kk = 0; kk < 64; kk++) {
            float b0 = ws[tj * 2 + 0][kk];
            float b1 = ws[tj * 2 + 1][kk];
#pragma unroll
            for (int i = 0; i < 4; i++) {
                float a = xs[tt * 4 + i][kk];
                acc[i][0] = fmaf(a, b0, acc[i][0]);
                acc[i][1] = fmaf(a, b1, acc[i][1]);
            }
        }
        __syncthreads();
    }
    float bj0 = bias[j0 + tj * 2 + 0];
    float bj1 = bias[j0 + tj * 2 + 1];
#pragma unroll
    for (int i = 0; i < 4; i++) {
        int t = t0 + tt * 4 + i;
        if (t < TT) {
            d_gx[dir][(size_t)t * G4 + j0 + tj * 2 + 0] = acc[i][0] + bj0;
            d_gx[dir][(size_t)t * G4 + j0 + tj * 2 + 1] = acc[i][1] + bj1;
        }
    }
}

// ---------------- persistent bidirectional LSTM ----------------
// 64 blocks: [0,32) forward, [32,64) backward. 256 threads.
// Block bi owns h indices [bi*16, bi*16+16), i.e. 64 Whh rows (4 gates x 16),
// held entirely in registers (8 rows x 16 k per thread).
// Sync per step (R1-proven skeleton): warp 0 polls the 32 per-block flags
// (lane s watches flag[s]) with acquire loads, __syncthreads releases the
// block; compute; __syncthreads; warp 0 tail publishes h then release-stores
// its flag. Bounded spin converts any sync failure into wrong-but-terminating.
__global__ __launch_bounds__(256, 1) void lstm_kernel(const float* __restrict__ Wf_hh,
                                                      const float* __restrict__ Wb_hh) {
    int dir = blockIdx.x >> 5;
    int bi = blockIdx.x & 31;
    const float* Whh = dir ? Wb_hh : Wf_hh;
    int tid = threadIdx.x;
    int w = tid >> 5, s = tid & 31;

    __shared__ float gsum[64];     // dot results, indexed rr = q*4+g

    // Load this thread's Whh slice into registers: rows rr=w*8+p, k = j*128 + s*4 + e
    float4 wreg[8][4];
#pragma unroll
    for (int p = 0; p < 8; p++) {
        int rr = w * 8 + p;
        int q = rr >> 2, g = rr & 3;
        int grow = g * 512 + bi * 16 + q;
#pragma unroll
        for (int j = 0; j < 4; j++)
            wreg[p][j] = *(const float4*)&Whh[(size_t)grow * 512 + j * 128 + s * 4];
    }
    float c_reg = 0.f;
    unsigned int* flags = &d_flag[dir][0];

    for (int t = 0; t < TT; t++) {
        int ti = dir ? (TT - 1 - t) : t;

        // Prefetch gx for this step (independent of h)
        float gxv[4] = {0.f, 0.f, 0.f, 0.f};
        if (tid < 16) {
#pragma unroll
            for (int g = 0; g < 4; g++)
                gxv[g] = __ldcg(&d_gx[dir][(size_t)ti * G4 + g * 512 + bi * 16 + tid]);
        }

        if (t > 0) {
            if (w == 0) {
                unsigned int target = (unsigned)t;
                unsigned int f;
                int spins = 0;
                do {
                    f = ld_acquire(&flags[s]);
                } while (__any_sync(0xffffffffu, f < target) && ++spins < 100000);
            }
            __syncthreads();   // B1: release block once all producers published step t-1
        }

        float4 hv[4];
        if (t == 0) {
#pragma unroll
            for (int j = 0; j < 4; j++) hv[j] = make_float4(0.f, 0.f, 0.f, 0.f);
        } else {
            int tprev = dir ? (ti + 1) : (ti - 1);
#pragma unroll
            for (int j = 0; j < 4; j++)
                hv[j] = __ldcg((const float4*)&d_states[dir][(size_t)tprev * HH + j * 128 + s * 4]);
        }

        float acc[8] = {0.f, 0.f, 0.f, 0.f, 0.f, 0.f, 0.f, 0.f};
#pragma unroll
        for (int j = 0; j < 4; j++) {
            float4 hvj = hv[j];
#pragma unroll
            for (int p = 0; p < 8; p++) {
                float4 wv = wreg[p][j];
                acc[p] = fmaf(hvj.x, wv.x, acc[p]);
                acc[p] = fmaf(hvj.y, wv.y, acc[p]);
                acc[p] = fmaf(hvj.z, wv.z, acc[p]);
                acc[p] = fmaf(hvj.w, wv.w, acc[p]);
            }
        }
#pragma unroll
        for (int off = 16; off >= 1; off >>= 1) {
#pragma unroll
            for (int p = 0; p < 8; p++)
                acc[p] += __shfl_xor_sync(0xffffffffu, acc[p], off);
        }
        if (s < 8) {
            float v = acc[0];
            if (s == 1) v = acc[1]; else if (s == 2) v = acc[2]; else if (s == 3) v = acc[3];
            else if (s == 4) v = acc[4]; else if (s == 5) v = acc[5];
            else if (s == 6) v = acc[6]; else if (s == 7) v = acc[7];
            gsum[w * 8 + s] = v;
        }
        __syncthreads();       // B2: gsum complete

        if (tid < 16) {
            int q = tid;
            float gi = gsum[q * 4 + 0] + gxv[0];
            float gf = gsum[q * 4 + 1] + gxv[1];
            float gg = gsum[q * 4 + 2] + gxv[2];
            float go = gsum[q * 4 + 3] + gxv[3];
            float iv = 1.f / (1.f + __expf(-gi));
            float fv = 1.f / (1.f + __expf(-gf));
            float ov = 1.f / (1.f + __expf(-go));
            float c = fv * c_reg + iv * tanhf(gg);
            float h = ov * tanhf(c);
            c_reg = c;
            __stcg(&d_states[dir][(size_t)ti * HH + bi * 16 + q], h);
        }
        __syncwarp();          // warp 0: order h stores before flag release
        if (tid == 0) st_release(&flags[bi], (unsigned)(t + 1));
        // Other warps are held at B1 of step t+1 until warp 0 finishes this tail,
        // so gsum cannot be overwritten before warp 0 consumed it.
    }
}

// ---------------- E/F precompute ----------------
// E[t] = fwd[t] @ W1[0:512] - bwd[t+1] @ W1[512:1024]   (t in 0..384)
// F likewise with V1. grid: (16 jtiles, 13 ttiles, 2 which), 256 threads.
__global__ __launch_bounds__(256) void e_kernel(const float* __restrict__ W1,
                                                const float* __restrict__ V1) {
    int which = blockIdx.z;
    const float* B = which ? V1 : W1;
    float* outp = which ? d_F : d_E;
    int j0 = blockIdx.x * 64;
    int t0 = blockIdx.y * 32;
    __shared__ float as_[32][65];
    __shared__ float ws[64][65];
    int tid = threadIdx.x;
    int tt = tid >> 5, tj = tid & 31;
    float acc[4][2] = {};
    for (int kc = 0; kc < 16; kc++) {
        int half = kc >> 3;            // 0: fwd (+), 1: bwd[t+1] (-)
        int koff = (kc & 7) * 64;
#pragma unroll
        for (int i = 0; i < 2; i++) {
            int fi = tid + i * 256;
            int row = fi >> 4, q = fi & 15;
            float4 v = make_float4(0.f, 0.f, 0.f, 0.f);
            int trow = t0 + row;
            if (trow < NP1) {
                const float* src = half ? &d_states[1][(size_t)(trow + 1) * HH + koff + q * 4]
                                        : &d_states[0][(size_t)trow * HH + koff + q * 4];
                v = *(const float4*)src;
                if (half) { v.x = -v.x; v.y = -v.y; v.z = -v.z; v.w = -v.w; }
            }
            as_[row][q * 4 + 0] = v.x; as_[row][q * 4 + 1] = v.y;
            as_[row][q * 4 + 2] = v.z; as_[row][q * 4 + 3] = v.w;
        }
#pragma unroll
        for (int i = 0; i < 4; i++) {
            int fi = tid + i * 256;        // W tile [64k][64j]
            int k = fi >> 4, q = fi & 15;
            float4 v = *(const float4*)&B[(size_t)(half * 512 + koff + k) * 1024 + j0 + q * 4];
            ws[k][q * 4 + 0] = v.x; ws[k][q * 4 + 1] = v.y;
            ws[k][q * 4 + 2] = v.z; ws[k][q * 4 + 3] = v.w;
        }
        __syncthreads();
#pragma unroll 8
        for (int kk = 0; kk < 64; kk++) {
            float b0 = ws[kk][tj * 2 + 0];
            float b1 = ws[kk][tj * 2 + 1];
#pragma unroll
            for (int i = 0; i < 4; i++) {
                float a = as_[tt * 4 + i][kk];
                acc[i][0] = fmaf(a, b0, acc[i][0]);
                acc[i][1] = fmaf(a, b1, acc[i][1]);
            }
        }
        __syncthreads();
    }
#pragma unroll
    for (int i = 0; i < 4; i++) {
        int t = t0 + tt * 4 + i;
        if (t < NP1) {
            outp[(size_t)t * 1024 + j0 + tj * 2 + 0] = acc[i][0];
            outp[(size_t)t * 1024 + j0 + tj * 2 + 1] = acc[i][1];
        }
    }
}

// ---------------- span kernel ----------------
// block = (l = blockIdx.y, 64 r's starting at r0). 256 threads (16 tr x 16 tc).
// h1 = relu(E[r] - E[l] + b1); out[:,0:128] = h1 @ W2 + b2
// h2 = relu(F[r] - F[l] + c1); out[:,128]   = h2 . V2 + c2
#define SPAN_SMEM_FLOATS (1024 + 1024 + 1024 + 128 + 64 * 68 + 64 * 68 + 64 * 128)
__global__ __launch_bounds__(256) void span_kernel(const float* __restrict__ b1,
                                                   const float* __restrict__ W2,
                                                   const float* __restrict__ b2,
                                                   const float* __restrict__ c1,
                                                   const float* __restrict__ V2,
                                                   const float* __restrict__ c2,
                                                   float* __restrict__ out) {
    int l = blockIdx.y;
    int r0 = l + 1 + blockIdx.x * 64;
    if (r0 > 384) return;
    int nr = min(64, 385 - r0);

    extern __shared__ float sm[];
    float* base1 = sm;                 // 1024 : b1 - E[l]
    float* baseV = sm + 1024;          // 1024 : c1 - F[l]
    float* v2s   = sm + 2048;          // 1024
    float* b2s   = sm + 3072;          // 128
    float* h1s   = sm + 3200;          // 64 x 68
    float* h2s   = h1s + 64 * 68;      // 64 x 68
    float* w2s   = h2s + 64 * 68;      // 64 x 128

    int tid = threadIdx.x;
    int tr = tid >> 4, tc = tid & 15;

    ((float4*)base1)[tid] = f4sub(((const float4*)b1)[tid], ((const float4*)&d_E[(size_t)l * 1024])[tid]);
    ((float4*)baseV)[tid] = f4sub(((const float4*)c1)[tid], ((const float4*)&d_F[(size_t)l * 1024])[tid]);
    ((float4*)v2s)[tid] = ((const float4*)V2)[tid];
    if (tid < 32) ((float4*)b2s)[tid] = ((const float4*)b2)[tid];
    __syncthreads();

    float acc[4][8] = {};
    float sacc[4] = {0.f, 0.f, 0.f, 0.f};
    long sbase = (long)l * 384 - (long)l * (l - 1) / 2 + (r0 - l - 1);

    for (int kc = 0; kc < 16; kc++) {
#pragma unroll
        for (int i = 0; i < 4; i++) {
            int fi = tid + i * 256;          // 1024 f4: 64 rows x 16 quads
            int row = fi >> 4, q = fi & 15;
            int k = kc * 64 + q * 4;
            float4 e = make_float4(0.f, 0.f, 0.f, 0.f), f = e;
            if (row < nr) {
                e = *(const float4*)&d_E[(size_t)(r0 + row) * 1024 + k];
                f = *(const float4*)&d_F[(size_t)(r0 + row) * 1024 + k];
            }
            float4 h1 = f4relu(f4add(e, *(const float4*)&base1[k]));
            float4 h2 = f4relu(f4add(f, *(const float4*)&baseV[k]));
            *(float4*)&h1s[row * 68 + q * 4] = h1;
            *(float4*)&h2s[row * 68 + q * 4] = h2;
        }
#pragma unroll
        for (int i = 0; i < 8; i++) {
            int fi = tid + i * 256;          // 2048 f4: W2 tile [64k][128n]
            int k = fi >> 5, q = fi & 31;
            *(float4*)&w2s[k * 128 + q * 4] = *(const float4*)&W2[(size_t)(kc * 64 + k) * 128 + q * 4];
        }
        __syncthreads();

#pragma unroll 4
        for (int kk = 0; kk < 64; kk++) {
            float4 bb0 = *(const float4*)&w2s[kk * 128 + tc * 8];
            float4 bb1 = *(const float4*)&w2s[kk * 128 + tc * 8 + 4];
#pragma unroll
            for (int i = 0; i < 4; i++) {
                float a = h1s[(tr * 4 + i) * 68 + kk];
                acc[i][0] = fmaf(a, bb0.x, acc[i][0]);
                acc[i][1] = fmaf(a, bb0.y, acc[i][1]);
                acc[i][2] = fmaf(a, bb0.z, acc[i][2]);
                acc[i][3] = fmaf(a, bb0.w, acc[i][3]);
                acc[i][4] = fmaf(a, bb1.x, acc[i][4]);
                acc[i][5] = fmaf(a, bb1.y, acc[i][5]);
                acc[i][6] = fmaf(a, bb1.z, acc[i][6]);
                acc[i][7] = fmaf(a, bb1.w, acc[i][7]);
            }
        }
        // split-score partial: thread covers kk = tc*4 + m
#pragma unroll
        for (int m = 0; m < 4; m++) {
            int kk = tc * 4 + m;
            float v = v2s[kc * 64 + kk];
#pragma unroll
            for (int i = 0; i < 4; i++)
                sacc[i] = fmaf(h2s[(tr * 4 + i) * 68 + kk], v, sacc[i]);
        }
        __syncthreads();
    }

    // reduce split partials over tc (16 lanes within half-warp)
#pragma unroll
    for (int off = 1; off < 16; off <<= 1) {
#pragma unroll
        for (int i = 0; i < 4; i++)
            sacc[i] += __shfl_xor_sync(0xffffffffu, sacc[i], off);
    }
    float c2v = c2[0];
#pragma unroll
    for (int i = 0; i < 4; i++) {
        int row = tr * 4 + i;
        if (row < nr) {
            long s = sbase + row;
            float* orow = out + s * (long)OUTC;
#pragma unroll
            for (int jj = 0; jj < 8; jj++)
                orow[tc * 8 + jj] = acc[i][jj] + b2s[tc * 8 + jj];
            if (tc == 0) orow[128] = sacc[i] + c2v;
        }
    }
}

// ---------------- launch ----------------
extern "C" void kernel_launch(void* const* d_in, const int* in_sizes, int n_in,
                              void* d_out, int out_size) {
    const int* tag_ids = (const int*)d_in[0];
    const int* word_ids = (const int*)d_in[1];
    const float* tag_emb = (const float*)d_in[2];
    const float* word_emb = (const float*)d_in[3];
    const float* Wf_ih = (const float*)d_in[4];
    const float* Wf_hh = (const float*)d_in[5];
    const float* bf = (const float*)d_in[6];
    const float* Wb_ih = (const float*)d_in[7];
    const float* Wb_hh = (const float*)d_in[8];
    const float* bb = (const float*)d_in[9];
    const float* W1 = (const float*)d_in[10];
    const float* b1 = (const float*)d_in[11];
    const float* W2 = (const float*)d_in[12];
    const float* b2 = (const float*)d_in[13];
    const float* V1 = (const float*)d_in[14];
    const float* c1 = (const float*)d_in[15];
    const float* V2 = (const float*)d_in[16];
    const float* c2 = (const float*)d_in[17];
    float* out = (float*)d_out;

    size_t span_smem = (size_t)SPAN_SMEM_FLOATS * sizeof(float);
    cudaFuncSetAttribute(span_kernel, cudaFuncAttributeMaxDynamicSharedMemorySize, (int)span_smem);

    embed_kernel<<<TT, 128>>>(tag_ids, word_ids, tag_emb, word_emb);

    dim3 ggx(32, 13, 2);
    gx_kernel<<<ggx, 256>>>(Wf_ih, bf, Wb_ih, bb);

    lstm_kernel<<<64, 256>>>(Wf_hh, Wb_hh);

    dim3 ge(16, 13, 2);
    e_kernel<<<ge, 256>>>(W1, V1);

    dim3 gs(6, 384);
    span_kernel<<<gs, 256, span_smem>>>(b1, W2, b2, c1, V2, c2, out);

    (void)in_sizes; (void)n_in; (void)out_size;
}

// round 5
// speedup vs baseline: 1.3373x; 1.3373x over previous
#include <cuda_runtime.h>
#include <cuda_bf16.h>
#include <mma.h>
#include <math.h>

using namespace nvcuda;

// Inputs (metadata order):
// 0 tag_ids[386] i32, 1 word_ids[386] i32, 2 tag_emb[50,128], 3 word_emb[10000,384],
// 4 Wf_ih[2048,512], 5 Wf_hh[2048,512], 6 bf[2048], 7 Wb_ih[2048,512], 8 Wb_hh[2048,512], 9 bb[2048],
// 10 W1[1024,1024], 11 b1[1024], 12 W2[1024,128], 13 b2[128],
// 14 V1[1024,1024], 15 c1[1024], 16 V2[1024,1], 17 c2[1]
// Output: [73920, 129] f32

#define TT 386
#define HH 512
#define G4 2048
#define NP1 385
#define OUTC 129
#define LSTM_BD 32   // blocks per direction

// ------------- device scratch (no mallocs allowed) -------------
__device__ float d_x[TT * 512];
__device__ float d_gx[2][TT * G4];
__device__ float d_states[2][TT * HH];   // [0]=fwd[t], [1]=bwd[t] (original time index)
__device__ unsigned int d_flag[2][LSTM_BD];
__device__ float d_E[NP1 * 1024];
__device__ float d_F[NP1 * 1024];
__device__ __nv_bfloat16 d_W2hi[1024 * 128];
__device__ __nv_bfloat16 d_W2lo[1024 * 128];

static __device__ __forceinline__ float4 f4sub(float4 a, float4 b) {
    return make_float4(a.x - b.x, a.y - b.y, a.z - b.z, a.w - b.w);
}

static __device__ __forceinline__ unsigned int ld_acquire(const unsigned int* p) {
    unsigned int v;
    asm volatile("ld.acquire.gpu.global.u32 %0, [%1];" : "=r"(v) : "l"(p) : "memory");
    return v;
}
static __device__ __forceinline__ void st_release(unsigned int* p, unsigned int v) {
    asm volatile("st.release.gpu.global.u32 [%0], %1;" :: "l"(p), "r"(v) : "memory");
}

// ---------------- embed: x[t] = [tag_emb[tag], word_emb[word]]; also reset flags ----------------
__global__ void embed_kernel(const int* __restrict__ tag_ids, const int* __restrict__ word_ids,
                             const float* __restrict__ tag_emb, const float* __restrict__ word_emb) {
    int t = blockIdx.x;
    int tid = threadIdx.x;  // 128 threads: 128 float4 = 512 floats
    if (t == 0 && tid < 2 * LSTM_BD) ((unsigned int*)d_flag)[tid] = 0u;
    int tg = tag_ids[t], wd = word_ids[t];
    float4 v;
    if (tid < 32) v = ((const float4*)(tag_emb + (size_t)tg * 128))[tid];
    else          v = ((const float4*)(word_emb + (size_t)wd * 384))[tid - 32];
    ((float4*)(d_x + (size_t)t * 512))[tid] = v;
}

// ---------------- W2 bf16 hi/lo split ----------------
__global__ void w2split_kernel(const float* __restrict__ W2) {
    int i = blockIdx.x * blockDim.x + threadIdx.x;   // 0 .. 131071
    if (i < 1024 * 128) {
        float w = W2[i];
        __nv_bfloat16 hi = __float2bfloat16(w);
        d_W2hi[i] = hi;
        d_W2lo[i] = __float2bfloat16(w - __bfloat162float(hi));
    }
}

// ---------------- gx = x @ W_ih^T + b,  both directions ----------------
__global__ __launch_bounds__(256) void gx_kernel(const float* __restrict__ Wf, const float* __restrict__ bfv,
                                                 const float* __restrict__ Wb, const float* __restrict__ bbv) {
    int dir = blockIdx.z;
    const float* W = dir ? Wb : Wf;
    const float* bias = dir ? bbv : bfv;
    int j0 = blockIdx.x * 64;
    int t0 = blockIdx.y * 32;
    __shared__ float xs[32][65];
    __shared__ float ws[64][65];
    int tid = threadIdx.x;
    int tt = tid >> 5, tj = tid & 31;
    float acc[4][2] = {};
    for (int kc = 0; kc < 8; kc++) {
#pragma unroll
        for (int i = 0; i < 2; i++) {
            int fi = tid + i * 256;
            int row = fi >> 4, q = fi & 15;
            float4 v = make_float4(0.f, 0.f, 0.f, 0.f);
            if (t0 + row < TT) v = *(const float4*)&d_x[(size_t)(t0 + row) * 512 + kc * 64 + q * 4];
            xs[row][q * 4 + 0] = v.x; xs[row][q * 4 + 1] = v.y;
            xs[row][q * 4 + 2] = v.z; xs[row][q * 4 + 3] = v.w;
        }
#pragma unroll
        for (int i = 0; i < 4; i++) {
            int fi = tid + i * 256;
            int j = fi >> 4, q = fi & 15;
            float4 v = *(const float4*)&W[(size_t)(j0 + j) * 512 + kc * 64 + q * 4];
            ws[j][q * 4 + 0] = v.x; ws[j][q * 4 + 1] = v.y;
            ws[j][q * 4 + 2] = v.z; ws[j][q * 4 + 3] = v.w;
        }
        __syncthreads();
#pragma unroll 8
        for (int kk = 0; kk < 64; kk++) {
            float b0 = ws[tj * 2 + 0][kk];
            float b1 = ws[tj * 2 + 1][kk];
#pragma unroll
            for (int i = 0; i < 4; i++) {
                float a = xs[tt * 4 + i][kk];
                acc[i][0] = fmaf(a, b0, acc[i][0]);
                acc[i][1] = fmaf(a, b1, acc[i][1]);
            }
        }
        __syncthreads();
    }
    float bj0 = bias[j0 + tj * 2 + 0];
    float bj1 = bias[j0 + tj * 2 + 1];
#pragma unroll
    for (int i = 0; i < 4; i++) {
        int t = t0 + tt * 4 + i;
        if (t < TT) {
            d_gx[dir][(size_t)t * G4 + j0 + tj * 2 + 0] = acc[i][0] + bj0;
            d_gx[dir][(size_t)t * G4 + j0 + tj * 2 + 1] = acc[i][1] + bj1;
        }
    }
}

// ---------------- persistent bidirectional LSTM (R4-proven, unchanged) ----------------
__global__ __launch_bounds__(256, 1) void lstm_kernel(const float* __restrict__ Wf_hh,
                                                      const float* __restrict__ Wb_hh) {
    int dir = blockIdx.x >> 5;
    int bi = blockIdx.x & 31;
    const float* Whh = dir ? Wb_hh : Wf_hh;
    int tid = threadIdx.x;
    int w = tid >> 5, s = tid & 31;

    __shared__ float gsum[64];

    float4 wreg[8][4];
#pragma unroll
    for (int p = 0; p < 8; p++) {
        int rr = w * 8 + p;
        int q = rr >> 2, g = rr & 3;
        int grow = g * 512 + bi * 16 + q;
#pragma unroll
        for (int j = 0; j < 4; j++)
            wreg[p][j] = *(const float4*)&Whh[(size_t)grow * 512 + j * 128 + s * 4];
    }
    float c_reg = 0.f;
    unsigned int* flags = &d_flag[dir][0];

    for (int t = 0; t < TT; t++) {
        int ti = dir ? (TT - 1 - t) : t;

        float gxv[4] = {0.f, 0.f, 0.f, 0.f};
        if (tid < 16) {
#pragma unroll
            for (int g = 0; g < 4; g++)
                gxv[g] = __ldcg(&d_gx[dir][(size_t)ti * G4 + g * 512 + bi * 16 + tid]);
        }

        if (t > 0) {
            if (w == 0) {
                unsigned int target = (unsigned)t;
                unsigned int f;
                int spins = 0;
                do {
                    f = ld_acquire(&flags[s]);
                } while (__any_sync(0xffffffffu, f < target) && ++spins < 100000);
            }
            __syncthreads();   // B1
        }

        float4 hv[4];
        if (t == 0) {
#pragma unroll
            for (int j = 0; j < 4; j++) hv[j] = make_float4(0.f, 0.f, 0.f, 0.f);
        } else {
            int tprev = dir ? (ti + 1) : (ti - 1);
#pragma unroll
            for (int j = 0; j < 4; j++)
                hv[j] = __ldcg((const float4*)&d_states[dir][(size_t)tprev * HH + j * 128 + s * 4]);
        }

        float acc[8] = {0.f, 0.f, 0.f, 0.f, 0.f, 0.f, 0.f, 0.f};
#pragma unroll
        for (int j = 0; j < 4; j++) {
            float4 hvj = hv[j];
#pragma unroll
            for (int p = 0; p < 8; p++) {
                float4 wv = wreg[p][j];
                acc[p] = fmaf(hvj.x, wv.x, acc[p]);
                acc[p] = fmaf(hvj.y, wv.y, acc[p]);
                acc[p] = fmaf(hvj.z, wv.z, acc[p]);
                acc[p] = fmaf(hvj.w, wv.w, acc[p]);
            }
        }
#pragma unroll
        for (int off = 16; off >= 1; off >>= 1) {
#pragma unroll
            for (int p = 0; p < 8; p++)
                acc[p] += __shfl_xor_sync(0xffffffffu, acc[p], off);
        }
        if (s < 8) {
            float v = acc[0];
            if (s == 1) v = acc[1]; else if (s == 2) v = acc[2]; else if (s == 3) v = acc[3];
            else if (s == 4) v = acc[4]; else if (s == 5) v = acc[5];
            else if (s == 6) v = acc[6]; else if (s == 7) v = acc[7];
            gsum[w * 8 + s] = v;
        }
        __syncthreads();       // B2

        if (tid < 16) {
            int q = tid;
            float gi = gsum[q * 4 + 0] + gxv[0];
            float gf = gsum[q * 4 + 1] + gxv[1];
            float gg = gsum[q * 4 + 2] + gxv[2];
            float go = gsum[q * 4 + 3] + gxv[3];
            float iv = 1.f / (1.f + __expf(-gi));
            float fv = 1.f / (1.f + __expf(-gf));
            float ov = 1.f / (1.f + __expf(-go));
            float c = fv * c_reg + iv * tanhf(gg);
            float h = ov * tanhf(c);
            c_reg = c;
            __stcg(&d_states[dir][(size_t)ti * HH + bi * 16 + q], h);
        }
        __syncwarp();
        if (tid == 0) st_release(&flags[bi], (unsigned)(t + 1));
    }
}

// ---------------- E/F precompute (unchanged) ----------------
__global__ __launch_bounds__(256) void e_kernel(const float* __restrict__ W1,
                                                const float* __restrict__ V1) {
    int which = blockIdx.z;
    const float* B = which ? V1 : W1;
    float* outp = which ? d_F : d_E;
    int j0 = blockIdx.x * 64;
    int t0 = blockIdx.y * 32;
    __shared__ float as_[32][65];
    __shared__ float ws[64][65];
    int tid = threadIdx.x;
    int tt = tid >> 5, tj = tid & 31;
    float acc[4][2] = {};
    for (int kc = 0; kc < 16; kc++) {
        int half = kc >> 3;
        int koff = (kc & 7) * 64;
#pragma unroll
        for (int i = 0; i < 2; i++) {
            int fi = tid + i * 256;
            int row = fi >> 4, q = fi & 15;
            float4 v = make_float4(0.f, 0.f, 0.f, 0.f);
            int trow = t0 + row;
            if (trow < NP1) {
                const float* src = half ? &d_states[1][(size_t)(trow + 1) * HH + koff + q * 4]
                                        : &d_states[0][(size_t)trow * HH + koff + q * 4];
                v = *(const float4*)src;
                if (half) { v.x = -v.x; v.y = -v.y; v.z = -v.z; v.w = -v.w; }
            }
            as_[row][q * 4 + 0] = v.x; as_[row][q * 4 + 1] = v.y;
            as_[row][q * 4 + 2] = v.z; as_[row][q * 4 + 3] = v.w;
        }
#pragma unroll
        for (int i = 0; i < 4; i++) {
            int fi = tid + i * 256;
            int k = fi >> 4, q = fi & 15;
            float4 v = *(const float4*)&B[(size_t)(half * 512 + koff + k) * 1024 + j0 + q * 4];
            ws[k][q * 4 + 0] = v.x; ws[k][q * 4 + 1] = v.y;
            ws[k][q * 4 + 2] = v.z; ws[k][q * 4 + 3] = v.w;
        }
        __syncthreads();
#pragma unroll 8
        for (int kk = 0; kk < 64; kk++) {
            float b0 = ws[kk][tj * 2 + 0];
            float b1 = ws[kk][tj * 2 + 1];
#pragma unroll
            for (int i = 0; i < 4; i++) {
                float a = as_[tt * 4 + i][kk];
                acc[i][0] = fmaf(a, b0, acc[i][0]);
                acc[i][1] = fmaf(a, b1, acc[i][1]);
            }
        }
        __syncthreads();
    }
#pragma unroll
    for (int i = 0; i < 4; i++) {
        int t = t0 + tt * 4 + i;
        if (t < NP1) {
            outp[(size_t)t * 1024 + j0 + tj * 2 + 0] = acc[i][0];
            outp[(size_t)t * 1024 + j0 + tj * 2 + 1] = acc[i][1];
        }
    }
}

// ---------------- span kernel: tensor cores (bf16 hi/lo split) ----------------
// block = (l, 128 r's). 512 threads = 16 warps: warp (mw = w&3, nw = w>>2)
// owns 32m x 32n of the 128x128 output. K tiled by 64.
// h1 = relu(E[r]-E[l]+b1) split to bf16 hi/lo in smem; W2 hi/lo preloaded to smem.
// acc += Ahi*Bhi + Ahi*Blo + Alo*Bhi  (3 wmma, error ~2^-17).
// h2 = relu(F[r]-F[l]+c1) dotted with V2 in exact fp32 during formation.
#define TILE_R 128
// smem offsets (bytes)
#define SP_BASE1 0
#define SP_BASEV 4096
#define SP_V2    8192
#define SP_B2    12288
#define SP_AHI   12800
#define SP_ALO   31232
#define SP_BHI   49664
#define SP_BLO   67072
#define SP_TOTAL 84480
#define SP_STAGE SP_AHI   // f32[128][68] aliases Ahi/Alo after the mma loop

__global__ __launch_bounds__(512) void span_kernel(const float* __restrict__ b1,
                                                   const float* __restrict__ b2,
                                                   const float* __restrict__ c1,
                                                   const float* __restrict__ V2,
                                                   const float* __restrict__ c2,
                                                   float* __restrict__ out) {
    int l = blockIdx.y;
    int r0 = l + 1 + blockIdx.x * TILE_R;
    if (r0 > 384) return;
    int nr = min(TILE_R, 385 - r0);

    extern __shared__ char smem[];
    float* base1 = (float*)(smem + SP_BASE1);
    float* baseV = (float*)(smem + SP_BASEV);
    float* v2s   = (float*)(smem + SP_V2);
    float* b2s   = (float*)(smem + SP_B2);
    __nv_bfloat16* Ahi = (__nv_bfloat16*)(smem + SP_AHI);   // [128][72]
    __nv_bfloat16* Alo = (__nv_bfloat16*)(smem + SP_ALO);
    __nv_bfloat16* Bhi = (__nv_bfloat16*)(smem + SP_BHI);   // [64][136]
    __nv_bfloat16* Blo = (__nv_bfloat16*)(smem + SP_BLO);
    float* stage = (float*)(smem + SP_STAGE);               // [128][68]

    int tid = threadIdx.x;
    int wid = tid >> 5;
    int mw = wid & 3, nw = wid >> 2;

    if (tid < 256) {
        ((float4*)base1)[tid] = f4sub(((const float4*)b1)[tid], ((const float4*)&d_E[(size_t)l * 1024])[tid]);
        ((float4*)baseV)[tid] = f4sub(((const float4*)c1)[tid], ((const float4*)&d_F[(size_t)l * 1024])[tid]);
        ((float4*)v2s)[tid] = ((const float4*)V2)[tid];
        if (tid < 32) ((float4*)b2s)[tid] = ((const float4*)b2)[tid];
    }

    wmma::fragment<wmma::accumulator, 16, 16, 16, float> acc[2][2];
#pragma unroll
    for (int i = 0; i < 2; i++)
#pragma unroll
        for (int j = 0; j < 2; j++)
            wmma::fill_fragment(acc[i][j], 0.0f);

    float sacc[4] = {0.f, 0.f, 0.f, 0.f};
    long sbase = (long)l * 384 - (long)l * (l - 1) / 2 + (r0 - l - 1);
    __syncthreads();   // base1/baseV/v2s ready

    for (int kc = 0; kc < 16; kc++) {
        // ---- formation: A tile 128x64 (hi/lo bf16) + split-score partials ----
#pragma unroll
        for (int i = 0; i < 4; i++) {
            int fi = tid + i * 512;            // 2048 float4 slots: 128 rows x 16 quads
            int row = fi >> 4, q = fi & 15;
            int k = kc * 64 + q * 4;
            float4 e = make_float4(0.f, 0.f, 0.f, 0.f), f = e;
            if (row < nr) {
                e = *(const float4*)&d_E[(size_t)(r0 + row) * 1024 + k];
                f = *(const float4*)&d_F[(size_t)(r0 + row) * 1024 + k];
            }
            float4 bb = *(const float4*)&base1[k];
            float h0 = fmaxf(e.x + bb.x, 0.f), h1v = fmaxf(e.y + bb.y, 0.f);
            float h2v = fmaxf(e.z + bb.z, 0.f), h3 = fmaxf(e.w + bb.w, 0.f);
            __nv_bfloat16 a0 = __float2bfloat16(h0), a1 = __float2bfloat16(h1v);
            __nv_bfloat16 a2 = __float2bfloat16(h2v), a3 = __float2bfloat16(h3);
            int ab = row * 72 + q * 4;
            Ahi[ab + 0] = a0; Ahi[ab + 1] = a1; Ahi[ab + 2] = a2; Ahi[ab + 3] = a3;
            Alo[ab + 0] = __float2bfloat16(h0 - __bfloat162float(a0));
            Alo[ab + 1] = __float2bfloat16(h1v - __bfloat162float(a1));
            Alo[ab + 2] = __float2bfloat16(h2v - __bfloat162float(a2));
            Alo[ab + 3] = __float2bfloat16(h3 - __bfloat162float(a3));
            // split-score path (exact fp32)
            float4 bv = *(const float4*)&baseV[k];
            float4 vv = *(const float4*)&v2s[k];
            float t0 = fmaxf(f.x + bv.x, 0.f) * vv.x + fmaxf(f.y + bv.y, 0.f) * vv.y;
            float t1 = fmaxf(f.z + bv.z, 0.f) * vv.z + fmaxf(f.w + bv.w, 0.f) * vv.w;
            sacc[i] += t0 + t1;
        }
        // ---- B tile: W2 hi/lo rows [kc*64, +64) -> smem [64][136] ----
#pragma unroll
        for (int j = 0; j < 2; j++) {
            int idx = tid + j * 512;           // 1024 int4 = 64 rows x 16 int4 (8 bf16 each)
            int k = idx >> 4, c = idx & 15;
            const int4* srch = (const int4*)&d_W2hi[(size_t)(kc * 64 + k) * 128 + c * 8];
            const int4* srcl = (const int4*)&d_W2lo[(size_t)(kc * 64 + k) * 128 + c * 8];
            *(int4*)&Bhi[k * 136 + c * 8] = *srch;
            *(int4*)&Blo[k * 136 + c * 8] = *srcl;
        }
        __syncthreads();

        // ---- mma ----
#pragma unroll
        for (int kk = 0; kk < 4; kk++) {
            wmma::fragment<wmma::matrix_a, 16, 16, 16, __nv_bfloat16, wmma::row_major> ah[2], al[2];
            wmma::fragment<wmma::matrix_b, 16, 16, 16, __nv_bfloat16, wmma::row_major> bh[2], bl[2];
#pragma unroll
            for (int i = 0; i < 2; i++) {
                wmma::load_matrix_sync(ah[i], &Ahi[(mw * 32 + i * 16) * 72 + kk * 16], 72);
                wmma::load_matrix_sync(al[i], &Alo[(mw * 32 + i * 16) * 72 + kk * 16], 72);
            }
#pragma unroll
            for (int j = 0; j < 2; j++) {
                wmma::load_matrix_sync(bh[j], &Bhi[(kk * 16) * 136 + nw * 32 + j * 16], 136);
                wmma::load_matrix_sync(bl[j], &Blo[(kk * 16) * 136 + nw * 32 + j * 16], 136);
            }
#pragma unroll
            for (int i = 0; i < 2; i++)
#pragma unroll
                for (int j = 0; j < 2; j++) {
                    wmma::mma_sync(acc[i][j], ah[i], bh[j], acc[i][j]);
                    wmma::mma_sync(acc[i][j], ah[i], bl[j], acc[i][j]);
                    wmma::mma_sync(acc[i][j], al[i], bh[j], acc[i][j]);
                }
        }
        __syncthreads();   // protect A/B smem before next formation
    }

    // ---- split-score reduce (over 16 lanes sharing tid>>4) + write ----
#pragma unroll
    for (int off = 1; off < 16; off <<= 1) {
#pragma unroll
        for (int i = 0; i < 4; i++)
            sacc[i] += __shfl_xor_sync(0xffffffffu, sacc[i], off);
    }
    float c2v = c2[0];
    if ((tid & 15) == 0) {
#pragma unroll
        for (int i = 0; i < 4; i++) {
            int row = (tid >> 4) + i * 32;
            if (row < nr) out[(sbase + row) * (long)OUTC + 128] = sacc[i] + c2v;
        }
    }

    // ---- label scores: stage 64 cols at a time through smem ----
#pragma unroll
    for (int p = 0; p < 2; p++) {
        if ((nw >> 1) == p) {
#pragma unroll
            for (int i = 0; i < 2; i++)
#pragma unroll
                for (int j = 0; j < 2; j++)
                    wmma::store_matrix_sync(&stage[(mw * 32 + i * 16) * 68 + (nw & 1) * 32 + j * 16],
                                            acc[i][j], 68, wmma::mem_row_major);
        }
        __syncthreads();
#pragma unroll
        for (int j = 0; j < 16; j++) {
            int idx = tid + j * 512;           // 8192 = 128 rows x 64 cols
            int row = idx >> 6, c = idx & 63;
            if (row < nr)
                out[(sbase + row) * (long)OUTC + p * 64 + c] = stage[row * 68 + c] + b2s[p * 64 + c];
        }
        __syncthreads();
    }
}

// ---------------- launch ----------------
extern "C" void kernel_launch(void* const* d_in, const int* in_sizes, int n_in,
                              void* d_out, int out_size) {
    const int* tag_ids = (const int*)d_in[0];
    const int* word_ids = (const int*)d_in[1];
    const float* tag_emb = (const float*)d_in[2];
    const float* word_emb = (const float*)d_in[3];
    const float* Wf_ih = (const float*)d_in[4];
    const float* Wf_hh = (const float*)d_in[5];
    const float* bf = (const float*)d_in[6];
    const float* Wb_ih = (const float*)d_in[7];
    const float* Wb_hh = (const float*)d_in[8];
    const float* bb = (const float*)d_in[9];
    const float* W1 = (const float*)d_in[10];
    const float* b1 = (const float*)d_in[11];
    const float* W2 = (const float*)d_in[12];
    const float* b2 = (const float*)d_in[13];
    const float* V1 = (const float*)d_in[14];
    const float* c1 = (const float*)d_in[15];
    const float* V2 = (const float*)d_in[16];
    const float* c2 = (const float*)d_in[17];
    float* out = (float*)d_out;

    cudaFuncSetAttribute(span_kernel, cudaFuncAttributeMaxDynamicSharedMemorySize, SP_TOTAL);

    embed_kernel<<<TT, 128>>>(tag_ids, word_ids, tag_emb, word_emb);
    w2split_kernel<<<512, 256>>>(W2);

    dim3 ggx(32, 13, 2);
    gx_kernel<<<ggx, 256>>>(Wf_ih, bf, Wb_ih, bb);

    lstm_kernel<<<64, 256>>>(Wf_hh, Wb_hh);

    dim3 ge(16, 13, 2);
    e_kernel<<<ge, 256>>>(W1, V1);

    dim3 gs(3, 384);
    span_kernel<<<gs, 512, SP_TOTAL>>>(b1, b2, c1, V2, c2, out);

    (void)in_sizes; (void)n_in; (void)out_size;
}

// round 7
// speedup vs baseline: 1.4362x; 1.0739x over previous
#include <cuda_runtime.h>
#include <cuda_bf16.h>
#include <mma.h>
#include <math.h>

using namespace nvcuda;

// Inputs (metadata order):
// 0 tag_ids[386] i32, 1 word_ids[386] i32, 2 tag_emb[50,128], 3 word_emb[10000,384],
// 4 Wf_ih[2048,512], 5 Wf_hh[2048,512], 6 bf[2048], 7 Wb_ih[2048,512], 8 Wb_hh[2048,512], 9 bb[2048],
// 10 W1[1024,1024], 11 b1[1024], 12 W2[1024,128], 13 b2[128],
// 14 V1[1024,1024], 15 c1[1024], 16 V2[1024,1], 17 c2[1]
// Output: [73920, 129] f32

#define TT 386
#define HH 512
#define G4 2048
#define NP1 385
#define OUTC 129
#define LSTM_BD 32   // blocks per direction

// ------------- device scratch (no mallocs allowed) -------------
__device__ float d_x[TT * 512];
__device__ float d_gx[2][TT * G4];
__device__ float d_states[2][TT * HH];   // [0]=fwd[t], [1]=bwd[t] (original time index)
__device__ unsigned int d_flag[2][LSTM_BD];
__device__ float d_E[NP1 * 1024];
__device__ float d_F[NP1 * 1024];
__device__ __nv_bfloat16 d_W2hi[1024 * 128];
__device__ __nv_bfloat16 d_W2lo[1024 * 128];

static __device__ __forceinline__ float4 f4sub(float4 a, float4 b) {
    return make_float4(a.x - b.x, a.y - b.y, a.z - b.z, a.w - b.w);
}

static __device__ __forceinline__ float fast_sigmoid(float x) {
    return __fdividef(1.f, 1.f + __expf(-x));
}
static __device__ __forceinline__ float fast_tanh(float x) {
    x = fminf(fmaxf(x, -15.f), 15.f);
    float e = __expf(-2.f * x);
    return __fdividef(1.f - e, 1.f + e);
}

static __device__ __forceinline__ unsigned int ld_acquire(const unsigned int* p) {
    unsigned int v;
    asm volatile("ld.acquire.gpu.global.u32 %0, [%1];" : "=r"(v) : "l"(p) : "memory");
    return v;
}
static __device__ __forceinline__ void st_release(unsigned int* p, unsigned int v) {
    asm volatile("st.release.gpu.global.u32 [%0], %1;" :: "l"(p), "r"(v) : "memory");
}

// ---------------- embed: x[t] = [tag_emb[tag], word_emb[word]]; also reset flags ----------------
__global__ void embed_kernel(const int* __restrict__ tag_ids, const int* __restrict__ word_ids,
                             const float* __restrict__ tag_emb, const float* __restrict__ word_emb) {
    int t = blockIdx.x;
    int tid = threadIdx.x;  // 128 threads: 128 float4 = 512 floats
    if (t == 0 && tid < 2 * LSTM_BD) ((unsigned int*)d_flag)[tid] = 0u;
    int tg = tag_ids[t], wd = word_ids[t];
    float4 v;
    if (tid < 32) v = ((const float4*)(tag_emb + (size_t)tg * 128))[tid];
    else          v = ((const float4*)(word_emb + (size_t)wd * 384))[tid - 32];
    ((float4*)(d_x + (size_t)t * 512))[tid] = v;
}

// ---------------- W2 bf16 hi/lo split ----------------
__global__ void w2split_kernel(const float* __restrict__ W2) {
    int i = blockIdx.x * blockDim.x + threadIdx.x;
    if (i < 1024 * 128) {
        float w = W2[i];
        __nv_bfloat16 hi = __float2bfloat16(w);
        d_W2hi[i] = hi;
        d_W2lo[i] = __float2bfloat16(w - __bfloat162float(hi));
    }
}

// ---------------- gx = x @ W_ih^T + b,  both directions ----------------
__global__ __launch_bounds__(256) void gx_kernel(const float* __restrict__ Wf, const float* __restrict__ bfv,
                                                 const float* __restrict__ Wb, const float* __restrict__ bbv) {
    int dir = blockIdx.z;
    const float* W = dir ? Wb : Wf;
    const float* bias = dir ? bbv : bfv;
    int j0 = blockIdx.x * 64;
    int t0 = blockIdx.y * 32;
    __shared__ float xs[32][65];
    __shared__ float ws[64][65];
    int tid = threadIdx.x;
    int tt = tid >> 5, tj = tid & 31;
    float acc[4][2] = {};
    for (int kc = 0; kc < 8; kc++) {
#pragma unroll
        for (int i = 0; i < 2; i++) {
            int fi = tid + i * 256;
            int row = fi >> 4, q = fi & 15;
            float4 v = make_float4(0.f, 0.f, 0.f, 0.f);
            if (t0 + row < TT) v = *(const float4*)&d_x[(size_t)(t0 + row) * 512 + kc * 64 + q * 4];
            xs[row][q * 4 + 0] = v.x; xs[row][q * 4 + 1] = v.y;
            xs[row][q * 4 + 2] = v.z; xs[row][q * 4 + 3] = v.w;
        }
#pragma unroll
        for (int i = 0; i < 4; i++) {
            int fi = tid + i * 256;
            int j = fi >> 4, q = fi & 15;
            float4 v = *(const float4*)&W[(size_t)(j0 + j) * 512 + kc * 64 + q * 4];
            ws[j][q * 4 + 0] = v.x; ws[j][q * 4 + 1] = v.y;
            ws[j][q * 4 + 2] = v.z; ws[j][q * 4 + 3] = v.w;
        }
        __syncthreads();
#pragma unroll 8
        for (int kk = 0; kk < 64; kk++) {
            float b0 = ws[tj * 2 + 0][kk];
            float b1 = ws[tj * 2 + 1][kk];
#pragma unroll
            for (int i = 0; i < 4; i++) {
                float a = xs[tt * 4 + i][kk];
                acc[i][0] = fmaf(a, b0, acc[i][0]);
                acc[i][1] = fmaf(a, b1, acc[i][1]);
            }
        }
        __syncthreads();
    }
    float bj0 = bias[j0 + tj * 2 + 0];
    float bj1 = bias[j0 + tj * 2 + 1];
#pragma unroll
    for (int i = 0; i < 4; i++) {
        int t = t0 + tt * 4 + i;
        if (t < TT) {
            d_gx[dir][(size_t)t * G4 + j0 + tj * 2 + 0] = acc[i][0] + bj0;
            d_gx[dir][(size_t)t * G4 + j0 + tj * 2 + 1] = acc[i][1] + bj1;
        }
    }
}

// ---------------- persistent bidirectional LSTM (R4/R5-proven skeleton) ----------------
// 64 blocks: [0,32) forward, [32,64) backward. 256 threads.
// Block bi owns h indices [bi*16, bi*16+16) = 64 Whh rows, held in registers.
// Sync per step: ONLY warp 0 polls the 32 per-block flags (lane s watches
// flag[s]) with acquire loads; __syncthreads (B1) releases the block; compute;
// B2; warp 0 tail (fast sigmoid/tanh) publishes h then release-stores its flag.
__global__ __launch_bounds__(256, 1) void lstm_kernel(const float* __restrict__ Wf_hh,
                                                      const float* __restrict__ Wb_hh) {
    int dir = blockIdx.x >> 5;
    int bi = blockIdx.x & 31;
    const float* Whh = dir ? Wb_hh : Wf_hh;
    int tid = threadIdx.x;
    int w = tid >> 5, s = tid & 31;

    __shared__ float gsum[64];

    float4 wreg[8][4];
#pragma unroll
    for (int p = 0; p < 8; p++) {
        int rr = w * 8 + p;
        int q = rr >> 2, g = rr & 3;
        int grow = g * 512 + bi * 16 + q;
#pragma unroll
        for (int j = 0; j < 4; j++)
            wreg[p][j] = *(const float4*)&Whh[(size_t)grow * 512 + j * 128 + s * 4];
    }
    float c_reg = 0.f;
    unsigned int* flags = &d_flag[dir][0];

    for (int t = 0; t < TT; t++) {
        int ti = dir ? (TT - 1 - t) : t;

        // Prefetch gx for this step (independent of h)
        float gxv[4] = {0.f, 0.f, 0.f, 0.f};
        if (tid < 16) {
#pragma unroll
            for (int g = 0; g < 4; g++)
                gxv[g] = __ldcg(&d_gx[dir][(size_t)ti * G4 + g * 512 + bi * 16 + tid]);
        }

        if (t > 0) {
            if (w == 0) {
                unsigned int target = (unsigned)t;
                unsigned int f;
                int spins = 0;
                do {
                    f = ld_acquire(&flags[s]);
                } while (__any_sync(0xffffffffu, f < target) && ++spins < 100000);
            }
            __syncthreads();   // B1
        }

        float4 hv[4];
        if (t == 0) {
#pragma unroll
            for (int j = 0; j < 4; j++) hv[j] = make_float4(0.f, 0.f, 0.f, 0.f);
        } else {
            int tprev = dir ? (ti + 1) : (ti - 1);
#pragma unroll
            for (int j = 0; j < 4; j++)
                hv[j] = __ldcg((const float4*)&d_states[dir][(size_t)tprev * HH + j * 128 + s * 4]);
        }

        float acc[8] = {0.f, 0.f, 0.f, 0.f, 0.f, 0.f, 0.f, 0.f};
#pragma unroll
        for (int j = 0; j < 4; j++) {
            float4 hvj = hv[j];
#pragma unroll
            for (int p = 0; p < 8; p++) {
                float4 wv = wreg[p][j];
                acc[p] = fmaf(hvj.x, wv.x, acc[p]);
                acc[p] = fmaf(hvj.y, wv.y, acc[p]);
                acc[p] = fmaf(hvj.z, wv.z, acc[p]);
                acc[p] = fmaf(hvj.w, wv.w, acc[p]);
            }
        }
#pragma unroll
        for (int off = 16; off >= 1; off >>= 1) {
#pragma unroll
            for (int p = 0; p < 8; p++)
                acc[p] += __shfl_xor_sync(0xffffffffu, acc[p], off);
        }
        if (s < 8) {
            float v = acc[0];
            if (s == 1) v = acc[1]; else if (s == 2) v = acc[2]; else if (s == 3) v = acc[3];
            else if (s == 4) v = acc[4]; else if (s == 5) v = acc[5];
            else if (s == 6) v = acc[6]; else if (s == 7) v = acc[7];
            gsum[w * 8 + s] = v;
        }
        __syncthreads();       // B2

        if (tid < 16) {
            int q = tid;
            float gi = gsum[q * 4 + 0] + gxv[0];
            float gf = gsum[q * 4 + 1] + gxv[1];
            float gg = gsum[q * 4 + 2] + gxv[2];
            float go = gsum[q * 4 + 3] + gxv[3];
            float iv = fast_sigmoid(gi);
            float fv = fast_sigmoid(gf);
            float ov = fast_sigmoid(go);
            float c = fv * c_reg + iv * fast_tanh(gg);
            float h = ov * fast_tanh(c);
            c_reg = c;
            __stcg(&d_states[dir][(size_t)ti * HH + bi * 16 + q], h);
        }
        __syncwarp();
        if (tid == 0) st_release(&flags[bi], (unsigned)(t + 1));
    }
}

// ---------------- E/F precompute ----------------
// E[t] = fwd[t] @ W1[0:512] - bwd[t+1] @ W1[512:1024]; F likewise with V1.
__global__ __launch_bounds__(256) void e_kernel(const float* __restrict__ W1,
                                                const float* __restrict__ V1) {
    int which = blockIdx.z;
    const float* B = which ? V1 : W1;
    float* outp = which ? d_F : d_E;
    int j0 = blockIdx.x * 64;
    int t0 = blockIdx.y * 32;
    __shared__ float as_[32][65];
    __shared__ float ws[64][66];   // 66: float2 reads at even offsets stay conflict-free
    int tid = threadIdx.x;
    int tt = tid >> 5, tj = tid & 31;
    float acc[4][2] = {};
    for (int kc = 0; kc < 16; kc++) {
        int half = kc >> 3;
        int koff = (kc & 7) * 64;
#pragma unroll
        for (int i = 0; i < 2; i++) {
            int fi = tid + i * 256;
            int row = fi >> 4, q = fi & 15;
            float4 v = make_float4(0.f, 0.f, 0.f, 0.f);
            int trow = t0 + row;
            if (trow < NP1) {
                const float* src = half ? &d_states[1][(size_t)(trow + 1) * HH + koff + q * 4]
                                        : &d_states[0][(size_t)trow * HH + koff + q * 4];
                v = *(const float4*)src;
                if (half) { v.x = -v.x; v.y = -v.y; v.z = -v.z; v.w = -v.w; }
            }
            as_[row][q * 4 + 0] = v.x; as_[row][q * 4 + 1] = v.y;
            as_[row][q * 4 + 2] = v.z; as_[row][q * 4 + 3] = v.w;
        }
#pragma unroll
        for (int i = 0; i < 4; i++) {
            int fi = tid + i * 256;
            int k = fi >> 4, q = fi & 15;
            float4 v = *(const float4*)&B[(size_t)(half * 512 + koff + k) * 1024 + j0 + q * 4];
            ws[k][q * 4 + 0] = v.x; ws[k][q * 4 + 1] = v.y;
            ws[k][q * 4 + 2] = v.z; ws[k][q * 4 + 3] = v.w;
        }
        __syncthreads();
#pragma unroll 8
        for (int kk = 0; kk < 64; kk++) {
            float2 b01 = *(const float2*)&ws[kk][tj * 2];
#pragma unroll
            for (int i = 0; i < 4; i++) {
                float a = as_[tt * 4 + i][kk];
                acc[i][0] = fmaf(a, b01.x, acc[i][0]);
                acc[i][1] = fmaf(a, b01.y, acc[i][1]);
            }
        }
        __syncthreads();
    }
#pragma unroll
    for (int i = 0; i < 4; i++) {
        int t = t0 + tt * 4 + i;
        if (t < NP1) {
            outp[(size_t)t * 1024 + j0 + tj * 2 + 0] = acc[i][0];
            outp[(size_t)t * 1024 + j0 + tj * 2 + 1] = acc[i][1];
        }
    }
}

// ---------------- span kernel: tensor cores (bf16 hi/lo split, R5-proven) ----------------
#define TILE_R 128
#define SP_BASE1 0
#define SP_BASEV 4096
#define SP_V2    8192
#define SP_B2    12288
#define SP_AHI   12800
#define SP_ALO   31232
#define SP_BHI   49664
#define SP_BLO   67072
#define SP_TOTAL 84480
#define SP_STAGE SP_AHI

__global__ __launch_bounds__(512) void span_kernel(const float* __restrict__ b1,
                                                   const float* __restrict__ b2,
                                                   const float* __restrict__ c1,
                                                   const float* __restrict__ V2,
                                                   const float* __restrict__ c2,
                                                   float* __restrict__ out) {
    int l = blockIdx.y;
    int r0 = l + 1 + blockIdx.x * TILE_R;
    if (r0 > 384) return;
    int nr = min(TILE_R, 385 - r0);

    extern __shared__ char smem[];
    float* base1 = (float*)(smem + SP_BASE1);
    float* baseV = (float*)(smem + SP_BASEV);
    float* v2s   = (float*)(smem + SP_V2);
    float* b2s   = (float*)(smem + SP_B2);
    __nv_bfloat16* Ahi = (__nv_bfloat16*)(smem + SP_AHI);   // [128][72]
    __nv_bfloat16* Alo = (__nv_bfloat16*)(smem + SP_ALO);
    __nv_bfloat16* Bhi = (__nv_bfloat16*)(smem + SP_BHI);   // [64][136]
    __nv_bfloat16* Blo = (__nv_bfloat16*)(smem + SP_BLO);
    float* stage = (float*)(smem + SP_STAGE);               // [128][68]

    int tid = threadIdx.x;
    int wid = tid >> 5;
    int mw = wid & 3, nw = wid >> 2;

    if (tid < 256) {
        ((float4*)base1)[tid] = f4sub(((const float4*)b1)[tid], ((const float4*)&d_E[(size_t)l * 1024])[tid]);
        ((float4*)baseV)[tid] = f4sub(((const float4*)c1)[tid], ((const float4*)&d_F[(size_t)l * 1024])[tid]);
        ((float4*)v2s)[tid] = ((const float4*)V2)[tid];
        if (tid < 32) ((float4*)b2s)[tid] = ((const float4*)b2)[tid];
    }

    wmma::fragment<wmma::accumulator, 16, 16, 16, float> acc[2][2];
#pragma unroll
    for (int i = 0; i < 2; i++)
#pragma unroll
        for (int j = 0; j < 2; j++)
            wmma::fill_fragment(acc[i][j], 0.0f);

    float sacc[4] = {0.f, 0.f, 0.f, 0.f};
    long sbase = (long)l * 384 - (long)l * (l - 1) / 2 + (r0 - l - 1);
    __syncthreads();

    for (int kc = 0; kc < 16; kc++) {
#pragma unroll
        for (int i = 0; i < 4; i++) {
            int fi = tid + i * 512;
            int row = fi >> 4, q = fi & 15;
            int k = kc * 64 + q * 4;
            float4 e = make_float4(0.f, 0.f, 0.f, 0.f), f = e;
            if (row < nr) {
                e = *(const float4*)&d_E[(size_t)(r0 + row) * 1024 + k];
                f = *(const float4*)&d_F[(size_t)(r0 + row) * 1024 + k];
            }
            float4 bb = *(const float4*)&base1[k];
            float h0 = fmaxf(e.x + bb.x, 0.f), h1v = fmaxf(e.y + bb.y, 0.f);
            float h2v = fmaxf(e.z + bb.z, 0.f), h3 = fmaxf(e.w + bb.w, 0.f);
            __nv_bfloat16 a0 = __float2bfloat16(h0), a1 = __float2bfloat16(h1v);
            __nv_bfloat16 a2 = __float2bfloat16(h2v), a3 = __float2bfloat16(h3);
            int ab = row * 72 + q * 4;
            Ahi[ab + 0] = a0; Ahi[ab + 1] = a1; Ahi[ab + 2] = a2; Ahi[ab + 3] = a3;
            Alo[ab + 0] = __float2bfloat16(h0 - __bfloat162float(a0));
            Alo[ab + 1] = __float2bfloat16(h1v - __bfloat162float(a1));
            Alo[ab + 2] = __float2bfloat16(h2v - __bfloat162float(a2));
            Alo[ab + 3] = __float2bfloat16(h3 - __bfloat162float(a3));
            float4 bv = *(const float4*)&baseV[k];
            float4 vv = *(const float4*)&v2s[k];
            float t0 = fmaxf(f.x + bv.x, 0.f) * vv.x + fmaxf(f.y + bv.y, 0.f) * vv.y;
            float t1 = fmaxf(f.z + bv.z, 0.f) * vv.z + fmaxf(f.w + bv.w, 0.f) * vv.w;
            sacc[i] += t0 + t1;
        }
#pragma unroll
        for (int j = 0; j < 2; j++) {
            int idx = tid + j * 512;
            int k = idx >> 4, c = idx & 15;
            const int4* srch = (const int4*)&d_W2hi[(size_t)(kc * 64 + k) * 128 + c * 8];
            const int4* srcl = (const int4*)&d_W2lo[(size_t)(kc * 64 + k) * 128 + c * 8];
            *(int4*)&Bhi[k * 136 + c * 8] = *srch;
            *(int4*)&Blo[k * 136 + c * 8] = *srcl;
        }
        __syncthreads();

#pragma unroll
        for (int kk = 0; kk < 4; kk++) {
            wmma::fragment<wmma::matrix_a, 16, 16, 16, __nv_bfloat16, wmma::row_major> ah[2], al[2];
            wmma::fragment<wmma::matrix_b, 16, 16, 16, __nv_bfloat16, wmma::row_major> bh[2], bl[2];
#pragma unroll
            for (int i = 0; i < 2; i++) {
                wmma::load_matrix_sync(ah[i], &Ahi[(mw * 32 + i * 16) * 72 + kk * 16], 72);
                wmma::load_matrix_sync(al[i], &Alo[(mw * 32 + i * 16) * 72 + kk * 16], 72);
            }
#pragma unroll
            for (int j = 0; j < 2; j++) {
                wmma::load_matrix_sync(bh[j], &Bhi[(kk * 16) * 136 + nw * 32 + j * 16], 136);
                wmma::load_matrix_sync(bl[j], &Blo[(kk * 16) * 136 + nw * 32 + j * 16], 136);
            }
#pragma unroll
            for (int i = 0; i < 2; i++)
#pragma unroll
                for (int j = 0; j < 2; j++) {
                    wmma::mma_sync(acc[i][j], ah[i], bh[j], acc[i][j]);
                    wmma::mma_sync(acc[i][j], ah[i], bl[j], acc[i][j]);
                    wmma::mma_sync(acc[i][j], al[i], bh[j], acc[i][j]);
                }
        }
        __syncthreads();
    }

#pragma unroll
    for (int off = 1; off < 16; off <<= 1) {
#pragma unroll
        for (int i = 0; i < 4; i++)
            sacc[i] += __shfl_xor_sync(0xffffffffu, sacc[i], off);
    }
    float c2v = c2[0];
    if ((tid & 15) == 0) {
#pragma unroll
        for (int i = 0; i < 4; i++) {
            int row = (tid >> 4) + i * 32;
            if (row < nr) out[(sbase + row) * (long)OUTC + 128] = sacc[i] + c2v;
        }
    }

#pragma unroll
    for (int p = 0; p < 2; p++) {
        if ((nw >> 1) == p) {
#pragma unroll
            for (int i = 0; i < 2; i++)
#pragma unroll
                for (int j = 0; j < 2; j++)
                    wmma::store_matrix_sync(&stage[(mw * 32 + i * 16) * 68 + (nw & 1) * 32 + j * 16],
                                            acc[i][j], 68, wmma::mem_row_major);
        }
        __syncthreads();
#pragma unroll
        for (int j = 0; j < 16; j++) {
            int idx = tid + j * 512;
            int row = idx >> 6, c = idx & 63;
            if (row < nr)
                out[(sbase + row) * (long)OUTC + p * 64 + c] = stage[row * 68 + c] + b2s[p * 64 + c];
        }
        __syncthreads();
    }
}

// ---------------- launch ----------------
extern "C" void kernel_launch(void* const* d_in, const int* in_sizes, int n_in,
                              void* d_out, int out_size) {
    const int* tag_ids = (const int*)d_in[0];
    const int* word_ids = (const int*)d_in[1];
    const float* tag_emb = (const float*)d_in[2];
    const float* word_emb = (const float*)d_in[3];
    const float* Wf_ih = (const float*)d_in[4];
    const float* Wf_hh = (const float*)d_in[5];
    const float* bf = (const float*)d_in[6];
    const float* Wb_ih = (const float*)d_in[7];
    const float* Wb_hh = (const float*)d_in[8];
    const float* bb = (const float*)d_in[9];
    const float* W1 = (const float*)d_in[10];
    const float* b1 = (const float*)d_in[11];
    const float* W2 = (const float*)d_in[12];
    const float* b2 = (const float*)d_in[13];
    const float* V1 = (const float*)d_in[14];
    const float* c1 = (const float*)d_in[15];
    const float* V2 = (const float*)d_in[16];
    const float* c2 = (const float*)d_in[17];
    float* out = (float*)d_out;

    cudaFuncSetAttribute(span_kernel, cudaFuncAttributeMaxDynamicSharedMemorySize, SP_TOTAL);

    embed_kernel<<<TT, 128>>>(tag_ids, word_ids, tag_emb, word_emb);
    w2split_kernel<<<512, 256>>>(W2);

    dim3 ggx(32, 13, 2);
    gx_kernel<<<ggx, 256>>>(Wf_ih, bf, Wb_ih, bb);

    lstm_kernel<<<64, 256>>>(Wf_hh, Wb_hh);

    dim3 ge(16, 13, 2);
    e_kernel<<<ge, 256>>>(W1, V1);

    dim3 gs(3, 384);
    span_kernel<<<gs, 512, SP_TOTAL>>>(b1, b2, c1, V2, c2, out);

    (void)in_sizes; (void)n_in; (void)out_size;
}

// round 8
// speedup vs baseline: 1.5559x; 1.0834x over previous
#include <cuda_runtime.h>
#include <cuda_bf16.h>
#include <mma.h>
#include <math.h>

using namespace nvcuda;

// Inputs (metadata order):
// 0 tag_ids[386] i32, 1 word_ids[386] i32, 2 tag_emb[50,128], 3 word_emb[10000,384],
// 4 Wf_ih[2048,512], 5 Wf_hh[2048,512], 6 bf[2048], 7 Wb_ih[2048,512], 8 Wb_hh[2048,512], 9 bb[2048],
// 10 W1[1024,1024], 11 b1[1024], 12 W2[1024,128], 13 b2[128],
// 14 V1[1024,1024], 15 c1[1024], 16 V2[1024,1], 17 c2[1]
// Output: [73920, 129] f32

#define TT 386
#define HH 512
#define G4 2048
#define NP1 385
#define OUTC 129
#define LSTM_BD 32   // blocks per direction

// ------------- device scratch (no mallocs allowed) -------------
__device__ float d_x[TT * 512];
__device__ float d_gx[2][TT * G4];
__device__ float d_states[2][TT * HH];   // [0]=fwd[t], [1]=bwd[t] (original time index)
__device__ unsigned int d_flag[2][LSTM_BD];
__device__ float d_E[NP1 * 1024];
__device__ float d_F[NP1 * 1024];
__device__ __nv_bfloat16 d_W2hi[1024 * 128];
__device__ __nv_bfloat16 d_W2lo[1024 * 128];

static __device__ __forceinline__ float4 f4sub(float4 a, float4 b) {
    return make_float4(a.x - b.x, a.y - b.y, a.z - b.z, a.w - b.w);
}

static __device__ __forceinline__ float fast_sigmoid(float x) {
    return __fdividef(1.f, 1.f + __expf(-x));
}
static __device__ __forceinline__ float fast_tanh(float x) {
    x = fminf(fmaxf(x, -15.f), 15.f);
    float e = __expf(-2.f * x);
    return __fdividef(1.f - e, 1.f + e);
}

static __device__ __forceinline__ unsigned int ld_acquire(const unsigned int* p) {
    unsigned int v;
    asm volatile("ld.acquire.gpu.global.u32 %0, [%1];" : "=r"(v) : "l"(p) : "memory");
    return v;
}
static __device__ __forceinline__ void st_release(unsigned int* p, unsigned int v) {
    asm volatile("st.release.gpu.global.u32 [%0], %1;" :: "l"(p), "r"(v) : "memory");
}

// packed f32x2 helpers (Blackwell sm_100a)
static __device__ __forceinline__ unsigned long long pack2(float lo, float hi) {
    unsigned long long r;
    asm("mov.b64 %0, {%1, %2};" : "=l"(r) : "f"(lo), "f"(hi));
    return r;
}
static __device__ __forceinline__ void unpack2(unsigned long long v, float& lo, float& hi) {
    asm("mov.b64 {%0, %1}, %2;" : "=f"(lo), "=f"(hi) : "l"(v));
}
static __device__ __forceinline__ unsigned long long fma2(unsigned long long a, unsigned long long b,
                                                          unsigned long long c) {
    unsigned long long d;
    asm("fma.rn.f32x2 %0, %1, %2, %3;" : "=l"(d) : "l"(a), "l"(b), "l"(c));
    return d;
}

// ---------------- embed: x[t] = [tag_emb[tag], word_emb[word]]; also reset flags ----------------
__global__ void embed_kernel(const int* __restrict__ tag_ids, const int* __restrict__ word_ids,
                             const float* __restrict__ tag_emb, const float* __restrict__ word_emb) {
    int t = blockIdx.x;
    int tid = threadIdx.x;  // 128 threads: 128 float4 = 512 floats
    if (t == 0 && tid < 2 * LSTM_BD) ((unsigned int*)d_flag)[tid] = 0u;
    int tg = tag_ids[t], wd = word_ids[t];
    float4 v;
    if (tid < 32) v = ((const float4*)(tag_emb + (size_t)tg * 128))[tid];
    else          v = ((const float4*)(word_emb + (size_t)wd * 384))[tid - 32];
    ((float4*)(d_x + (size_t)t * 512))[tid] = v;
}

// ---------------- W2 bf16 hi/lo split ----------------
__global__ void w2split_kernel(const float* __restrict__ W2) {
    int i = blockIdx.x * blockDim.x + threadIdx.x;
    if (i < 1024 * 128) {
        float w = W2[i];
        __nv_bfloat16 hi = __float2bfloat16(w);
        d_W2hi[i] = hi;
        d_W2lo[i] = __float2bfloat16(w - __bfloat162float(hi));
    }
}

// ---------------- gx = x @ W_ih^T + b,  both directions ----------------
__global__ __launch_bounds__(256) void gx_kernel(const float* __restrict__ Wf, const float* __restrict__ bfv,
                                                 const float* __restrict__ Wb, const float* __restrict__ bbv) {
    int dir = blockIdx.z;
    const float* W = dir ? Wb : Wf;
    const float* bias = dir ? bbv : bfv;
    int j0 = blockIdx.x * 64;
    int t0 = blockIdx.y * 32;
    __shared__ float xs[32][65];
    __shared__ float ws[64][65];
    int tid = threadIdx.x;
    int tt = tid >> 5, tj = tid & 31;
    float acc[4][2] = {};
    for (int kc = 0; kc < 8; kc++) {
#pragma unroll
        for (int i = 0; i < 2; i++) {
            int fi = tid + i * 256;
            int row = fi >> 4, q = fi & 15;
            float4 v = make_float4(0.f, 0.f, 0.f, 0.f);
            if (t0 + row < TT) v = *(const float4*)&d_x[(size_t)(t0 + row) * 512 + kc * 64 + q * 4];
            xs[row][q * 4 + 0] = v.x; xs[row][q * 4 + 1] = v.y;
            xs[row][q * 4 + 2] = v.z; xs[row][q * 4 + 3] = v.w;
        }
#pragma unroll
        for (int i = 0; i < 4; i++) {
            int fi = tid + i * 256;
            int j = fi >> 4, q = fi & 15;
            float4 v = *(const float4*)&W[(size_t)(j0 + j) * 512 + kc * 64 + q * 4];
            ws[j][q * 4 + 0] = v.x; ws[j][q * 4 + 1] = v.y;
            ws[j][q * 4 + 2] = v.z; ws[j][q * 4 + 3] = v.w;
        }
        __syncthreads();
#pragma unroll 8
        for (int kk = 0; kk < 64; kk++) {
            float b0 = ws[tj * 2 + 0][kk];
            float b1 = ws[tj * 2 + 1][kk];
#pragma unroll
            for (int i = 0; i < 4; i++) {
                float a = xs[tt * 4 + i][kk];
                acc[i][0] = fmaf(a, b0, acc[i][0]);
                acc[i][1] = fmaf(a, b1, acc[i][1]);
            }
        }
        __syncthreads();
    }
    float bj0 = bias[j0 + tj * 2 + 0];
    float bj1 = bias[j0 + tj * 2 + 1];
#pragma unroll
    for (int i = 0; i < 4; i++) {
        int t = t0 + tt * 4 + i;
        if (t < TT) {
            d_gx[dir][(size_t)t * G4 + j0 + tj * 2 + 0] = acc[i][0] + bj0;
            d_gx[dir][(size_t)t * G4 + j0 + tj * 2 + 1] = acc[i][1] + bj1;
        }
    }
}

// ---------------- persistent bidirectional LSTM ----------------
// 64 blocks: [0,32) forward, [32,64) backward. 256 threads, 8 warps.
// Block bi owns h indices [bi*16, bi*16+16) = 64 Whh rows, in registers
// (packed f32x2: 64 fma2/thread/step). Sync skeleton IDENTICAL to R7
// (proven): warp 0 acquire-polls the 32 per-block flags, B1 __syncthreads
// releases the block; compute; B2 __syncthreads; tid0 release-stores flag.
// Tail is now in-warp: after the butterfly every lane holds all 8 row sums,
// so lanes 0/1 of warp w compute h(2w)/h(2w+1) directly (no gsum smem,
// no 16-thread serialized tail).
__global__ __launch_bounds__(256, 1) void lstm_kernel(const float* __restrict__ Wf_hh,
                                                      const float* __restrict__ Wb_hh) {
    int dir = blockIdx.x >> 5;
    int bi = blockIdx.x & 31;
    const float* Whh = dir ? Wb_hh : Wf_hh;
    int tid = threadIdx.x;
    int w = tid >> 5, s = tid & 31;

    // Whh slice packed into f32x2 registers: rows rr=w*8+p, k = j*128 + s*4
    unsigned long long wp[8][4][2];
#pragma unroll
    for (int p = 0; p < 8; p++) {
        int rr = w * 8 + p;
        int q = rr >> 2, g = rr & 3;
        int grow = g * 512 + bi * 16 + q;
#pragma unroll
        for (int j = 0; j < 4; j++) {
            float4 wv = *(const float4*)&Whh[(size_t)grow * 512 + j * 128 + s * 4];
            wp[p][j][0] = pack2(wv.x, wv.y);
            wp[p][j][1] = pack2(wv.z, wv.w);
        }
    }
    float c_reg = 0.f;
    unsigned int* flags = &d_flag[dir][0];

    for (int t = 0; t < TT; t++) {
        int ti = dir ? (TT - 1 - t) : t;

        // gx for this step: lane p<8 of warp w owns row rr=w*8+p
        float gxv = 0.f;
        if (s < 8) {
            int q = 2 * w + (s >> 2), g = s & 3;
            gxv = __ldcg(&d_gx[dir][(size_t)ti * G4 + g * 512 + bi * 16 + q]);
        }

        if (t > 0) {
            if (w == 0) {
                unsigned int target = (unsigned)t;
                unsigned int f;
                int spins = 0;
                do {
                    f = ld_acquire(&flags[s]);
                } while (__any_sync(0xffffffffu, f < target) && ++spins < 100000);
            }
            __syncthreads();   // B1
        }

        float4 hv[4];
        if (t == 0) {
#pragma unroll
            for (int j = 0; j < 4; j++) hv[j] = make_float4(0.f, 0.f, 0.f, 0.f);
        } else {
            int tprev = dir ? (ti + 1) : (ti - 1);
#pragma unroll
            for (int j = 0; j < 4; j++)
                hv[j] = __ldcg((const float4*)&d_states[dir][(size_t)tprev * HH + j * 128 + s * 4]);
        }

        unsigned long long acc2[8] = {0ull, 0ull, 0ull, 0ull, 0ull, 0ull, 0ull, 0ull};
#pragma unroll
        for (int j = 0; j < 4; j++) {
            unsigned long long hp0 = pack2(hv[j].x, hv[j].y);
            unsigned long long hp1 = pack2(hv[j].z, hv[j].w);
#pragma unroll
            for (int p = 0; p < 8; p++) {
                acc2[p] = fma2(hp0, wp[p][j][0], acc2[p]);
                acc2[p] = fma2(hp1, wp[p][j][1], acc2[p]);
            }
        }
        float acc[8];
#pragma unroll
        for (int p = 0; p < 8; p++) {
            float lo, hi;
            unpack2(acc2[p], lo, hi);
            acc[p] = lo + hi;
        }
#pragma unroll
        for (int off = 16; off >= 1; off >>= 1) {
#pragma unroll
            for (int p = 0; p < 8; p++)
                acc[p] += __shfl_xor_sync(0xffffffffu, acc[p], off);
        }
        // gather gx to the two gate lanes (shfl by full warp; only s<2 consume)
        float gx0 = __shfl_sync(0xffffffffu, gxv, (s * 4 + 0) & 31);
        float gx1 = __shfl_sync(0xffffffffu, gxv, (s * 4 + 1) & 31);
        float gx2 = __shfl_sync(0xffffffffu, gxv, (s * 4 + 2) & 31);
        float gx3 = __shfl_sync(0xffffffffu, gxv, (s * 4 + 3) & 31);

        if (s < 2) {
            float a0, a1, a2, a3;
            if (s == 0) { a0 = acc[0]; a1 = acc[1]; a2 = acc[2]; a3 = acc[3]; }
            else        { a0 = acc[4]; a1 = acc[5]; a2 = acc[6]; a3 = acc[7]; }
            float gi = a0 + gx0;
            float gf = a1 + gx1;
            float gg = a2 + gx2;
            float go = a3 + gx3;
            float iv = fast_sigmoid(gi);
            float fv = fast_sigmoid(gf);
            float ov = fast_sigmoid(go);
            float c = fv * c_reg + iv * fast_tanh(gg);
            float h = ov * fast_tanh(c);
            c_reg = c;
            __stcg(&d_states[dir][(size_t)ti * HH + bi * 16 + 2 * w + s], h);
        }
        __syncthreads();       // B2: all warps' h stores done before release
        if (tid == 0) st_release(&flags[bi], (unsigned)(t + 1));
    }
}

// ---------------- E/F precompute ----------------
// E[t] = fwd[t] @ W1[0:512] - bwd[t+1] @ W1[512:1024]; F likewise with V1.
__global__ __launch_bounds__(256) void e_kernel(const float* __restrict__ W1,
                                                const float* __restrict__ V1) {
    int which = blockIdx.z;
    const float* B = which ? V1 : W1;
    float* outp = which ? d_F : d_E;
    int j0 = blockIdx.x * 64;
    int t0 = blockIdx.y * 32;
    __shared__ float as_[32][65];
    __shared__ float ws[64][66];   // 66: float2 reads at even offsets stay conflict-free
    int tid = threadIdx.x;
    int tt = tid >> 5, tj = tid & 31;
    float acc[4][2] = {};
    for (int kc = 0; kc < 16; kc++) {
        int half = kc >> 3;
        int koff = (kc & 7) * 64;
#pragma unroll
        for (int i = 0; i < 2; i++) {
            int fi = tid + i * 256;
            int row = fi >> 4, q = fi & 15;
            float4 v = make_float4(0.f, 0.f, 0.f, 0.f);
            int trow = t0 + row;
            if (trow < NP1) {
                const float* src = half ? &d_states[1][(size_t)(trow + 1) * HH + koff + q * 4]
                                        : &d_states[0][(size_t)trow * HH + koff + q * 4];
                v = *(const float4*)src;
                if (half) { v.x = -v.x; v.y = -v.y; v.z = -v.z; v.w = -v.w; }
            }
            as_[row][q * 4 + 0] = v.x; as_[row][q * 4 + 1] = v.y;
            as_[row][q * 4 + 2] = v.z; as_[row][q * 4 + 3] = v.w;
        }
#pragma unroll
        for (int i = 0; i < 4; i++) {
            int fi = tid + i * 256;
            int k = fi >> 4, q = fi & 15;
            float4 v = *(const float4*)&B[(size_t)(half * 512 + koff + k) * 1024 + j0 + q * 4];
            ws[k][q * 4 + 0] = v.x; ws[k][q * 4 + 1] = v.y;
            ws[k][q * 4 + 2] = v.z; ws[k][q * 4 + 3] = v.w;
        }
        __syncthreads();
#pragma unroll 8
        for (int kk = 0; kk < 64; kk++) {
            float2 b01 = *(const float2*)&ws[kk][tj * 2];
#pragma unroll
            for (int i = 0; i < 4; i++) {
                float a = as_[tt * 4 + i][kk];
                acc[i][0] = fmaf(a, b01.x, acc[i][0]);
                acc[i][1] = fmaf(a, b01.y, acc[i][1]);
            }
        }
        __syncthreads();
    }
#pragma unroll
    for (int i = 0; i < 4; i++) {
        int t = t0 + tt * 4 + i;
        if (t < NP1) {
            outp[(size_t)t * 1024 + j0 + tj * 2 + 0] = acc[i][0];
            outp[(size_t)t * 1024 + j0 + tj * 2 + 1] = acc[i][1];
        }
    }
}

// ---------------- span kernel: tensor cores (bf16 hi/lo split, R5-proven) ----------------
#define TILE_R 128
#define SP_BASE1 0
#define SP_BASEV 4096
#define SP_V2    8192
#define SP_B2    12288
#define SP_AHI   12800
#define SP_ALO   31232
#define SP_BHI   49664
#define SP_BLO   67072
#define SP_TOTAL 84480
#define SP_STAGE SP_AHI

__global__ __launch_bounds__(512) void span_kernel(const float* __restrict__ b1,
                                                   const float* __restrict__ b2,
                                                   const float* __restrict__ c1,
                                                   const float* __restrict__ V2,
                                                   const float* __restrict__ c2,
                                                   float* __restrict__ out) {
    int l = blockIdx.y;
    int r0 = l + 1 + blockIdx.x * TILE_R;
    if (r0 > 384) return;
    int nr = min(TILE_R, 385 - r0);

    extern __shared__ char smem[];
    float* base1 = (float*)(smem + SP_BASE1);
    float* baseV = (float*)(smem + SP_BASEV);
    float* v2s   = (float*)(smem + SP_V2);
    float* b2s   = (float*)(smem + SP_B2);
    __nv_bfloat16* Ahi = (__nv_bfloat16*)(smem + SP_AHI);   // [128][72]
    __nv_bfloat16* Alo = (__nv_bfloat16*)(smem + SP_ALO);
    __nv_bfloat16* Bhi = (__nv_bfloat16*)(smem + SP_BHI);   // [64][136]
    __nv_bfloat16* Blo = (__nv_bfloat16*)(smem + SP_BLO);
    float* stage = (float*)(smem + SP_STAGE);               // [128][68]

    int tid = threadIdx.x;
    int wid = tid >> 5;
    int mw = wid & 3, nw = wid >> 2;

    if (tid < 256) {
        ((float4*)base1)[tid] = f4sub(((const float4*)b1)[tid], ((const float4*)&d_E[(size_t)l * 1024])[tid]);
        ((float4*)baseV)[tid] = f4sub(((const float4*)c1)[tid], ((const float4*)&d_F[(size_t)l * 1024])[tid]);
        ((float4*)v2s)[tid] = ((const float4*)V2)[tid];
        if (tid < 32) ((float4*)b2s)[tid] = ((const float4*)b2)[tid];
    }

    wmma::fragment<wmma::accumulator, 16, 16, 16, float> acc[2][2];
#pragma unroll
    for (int i = 0; i < 2; i++)
#pragma unroll
        for (int j = 0; j < 2; j++)
            wmma::fill_fragment(acc[i][j], 0.0f);

    float sacc[4] = {0.f, 0.f, 0.f, 0.f};
    long sbase = (long)l * 384 - (long)l * (l - 1) / 2 + (r0 - l - 1);
    __syncthreads();

    for (int kc = 0; kc < 16; kc++) {
#pragma unroll
        for (int i = 0; i < 4; i++) {
            int fi = tid + i * 512;
            int row = fi >> 4, q = fi & 15;
            int k = kc * 64 + q * 4;
            float4 e = make_float4(0.f, 0.f, 0.f, 0.f), f = e;
            if (row < nr) {
                e = *(const float4*)&d_E[(size_t)(r0 + row) * 1024 + k];
                f = *(const float4*)&d_F[(size_t)(r0 + row) * 1024 + k];
            }
            float4 bb = *(const float4*)&base1[k];
            float h0 = fmaxf(e.x + bb.x, 0.f), h1v = fmaxf(e.y + bb.y, 0.f);
            float h2v = fmaxf(e.z + bb.z, 0.f), h3 = fmaxf(e.w + bb.w, 0.f);
            __nv_bfloat16 a0 = __float2bfloat16(h0), a1 = __float2bfloat16(h1v);
            __nv_bfloat16 a2 = __float2bfloat16(h2v), a3 = __float2bfloat16(h3);
            int ab = row * 72 + q * 4;
            Ahi[ab + 0] = a0; Ahi[ab + 1] = a1; Ahi[ab + 2] = a2; Ahi[ab + 3] = a3;
            Alo[ab + 0] = __float2bfloat16(h0 - __bfloat162float(a0));
            Alo[ab + 1] = __float2bfloat16(h1v - __bfloat162float(a1));
            Alo[ab + 2] = __float2bfloat16(h2v - __bfloat162float(a2));
            Alo[ab + 3] = __float2bfloat16(h3 - __bfloat162float(a3));
            float4 bv = *(const float4*)&baseV[k];
            float4 vv = *(const float4*)&v2s[k];
            float t0 = fmaxf(f.x + bv.x, 0.f) * vv.x + fmaxf(f.y + bv.y, 0.f) * vv.y;
            float t1 = fmaxf(f.z + bv.z, 0.f) * vv.z + fmaxf(f.w + bv.w, 0.f) * vv.w;
            sacc[i] += t0 + t1;
        }
#pragma unroll
        for (int j = 0; j < 2; j++) {
            int idx = tid + j * 512;
            int k = idx >> 4, c = idx & 15;
            const int4* srch = (const int4*)&d_W2hi[(size_t)(kc * 64 + k) * 128 + c * 8];
            const int4* srcl = (const int4*)&d_W2lo[(size_t)(kc * 64 + k) * 128 + c * 8];
            *(int4*)&Bhi[k * 136 + c * 8] = *srch;
            *(int4*)&Blo[k * 136 + c * 8] = *srcl;
        }
        __syncthreads();

#pragma unroll
        for (int kk = 0; kk < 4; kk++) {
            wmma::fragment<wmma::matrix_a, 16, 16, 16, __nv_bfloat16, wmma::row_major> ah[2], al[2];
            wmma::fragment<wmma::matrix_b, 16, 16, 16, __nv_bfloat16, wmma::row_major> bh[2], bl[2];
#pragma unroll
            for (int i = 0; i < 2; i++) {
                wmma::load_matrix_sync(ah[i], &Ahi[(mw * 32 + i * 16) * 72 + kk * 16], 72);
                wmma::load_matrix_sync(al[i], &Alo[(mw * 32 + i * 16) * 72 + kk * 16], 72);
            }
#pragma unroll
            for (int j = 0; j < 2; j++) {
                wmma::load_matrix_sync(bh[j], &Bhi[(kk * 16) * 136 + nw * 32 + j * 16], 136);
                wmma::load_matrix_sync(bl[j], &Blo[(kk * 16) * 136 + nw * 32 + j * 16], 136);
            }
#pragma unroll
            for (int i = 0; i < 2; i++)
#pragma unroll
                for (int j = 0; j < 2; j++) {
                    wmma::mma_sync(acc[i][j], ah[i], bh[j], acc[i][j]);
                    wmma::mma_sync(acc[i][j], ah[i], bl[j], acc[i][j]);
                    wmma::mma_sync(acc[i][j], al[i], bh[j], acc[i][j]);
                }
        }
        __syncthreads();
    }

#pragma unroll
    for (int off = 1; off < 16; off <<= 1) {
#pragma unroll
        for (int i = 0; i < 4; i++)
            sacc[i] += __shfl_xor_sync(0xffffffffu, sacc[i], off);
    }
    float c2v = c2[0];
    if ((tid & 15) == 0) {
#pragma unroll
        for (int i = 0; i < 4; i++) {
            int row = (tid >> 4) + i * 32;
            if (row < nr) out[(sbase + row) * (long)OUTC + 128] = sacc[i] + c2v;
        }
    }

#pragma unroll
    for (int p = 0; p < 2; p++) {
        if ((nw >> 1) == p) {
#pragma unroll
            for (int i = 0; i < 2; i++)
#pragma unroll
                for (int j = 0; j < 2; j++)
                    wmma::store_matrix_sync(&stage[(mw * 32 + i * 16) * 68 + (nw & 1) * 32 + j * 16],
                                            acc[i][j], 68, wmma::mem_row_major);
        }
        __syncthreads();
#pragma unroll
        for (int j = 0; j < 16; j++) {
            int idx = tid + j * 512;
            int row = idx >> 6, c = idx & 63;
            if (row < nr)
                out[(sbase + row) * (long)OUTC + p * 64 + c] = stage[row * 68 + c] + b2s[p * 64 + c];
        }
        __syncthreads();
    }
}

// ---------------- launch ----------------
extern "C" void kernel_launch(void* const* d_in, const int* in_sizes, int n_in,
                              void* d_out, int out_size) {
    const int* tag_ids = (const int*)d_in[0];
    const int* word_ids = (const int*)d_in[1];
    const float* tag_emb = (const float*)d_in[2];
    const float* word_emb = (const float*)d_in[3];
    const float* Wf_ih = (const float*)d_in[4];
    const float* Wf_hh = (const float*)d_in[5];
    const float* bf = (const float*)d_in[6];
    const float* Wb_ih = (const float*)d_in[7];
    const float* Wb_hh = (const float*)d_in[8];
    const float* bb = (const float*)d_in[9];
    const float* W1 = (const float*)d_in[10];
    const float* b1 = (const float*)d_in[11];
    const float* W2 = (const float*)d_in[12];
    const float* b2 = (const float*)d_in[13];
    const float* V1 = (const float*)d_in[14];
    const float* c1 = (const float*)d_in[15];
    const float* V2 = (const float*)d_in[16];
    const float* c2 = (const float*)d_in[17];
    float* out = (float*)d_out;

    cudaFuncSetAttribute(span_kernel, cudaFuncAttributeMaxDynamicSharedMemorySize, SP_TOTAL);

    embed_kernel<<<TT, 128>>>(tag_ids, word_ids, tag_emb, word_emb);
    w2split_kernel<<<512, 256>>>(W2);

    dim3 ggx(32, 13, 2);
    gx_kernel<<<ggx, 256>>>(Wf_ih, bf, Wb_ih, bb);

    lstm_kernel<<<64, 256>>>(Wf_hh, Wb_hh);

    dim3 ge(16, 13, 2);
    e_kernel<<<ge, 256>>>(W1, V1);

    dim3 gs(3, 384);
    span_kernel<<<gs, 512, SP_TOTAL>>>(b1, b2, c1, V2, c2, out);

    (void)in_sizes; (void)n_in; (void)out_size;
}